// round 3
// baseline (speedup 1.0000x reference)
#include <cuda_runtime.h>
#include <cstdint>

#define N_NODES 500000
#define HD      128
#define TM      128
#define THREADS 512
#define NTILES  ((N_NODES + TM - 1) / TM)   // 3907

// -------- SMEM layout (bytes, dynamic) --------
// A_x   [128 rows x 128 f32], 512B/row, xor-16 swizzle (pre-cvt to tf32; i_n stash after pass 0)
// A_red [128 rows x 128 f32], same swizzle, exact f32 (cvt on the fly for MMA)
// B stages: 2 x (384 rows x 32 f32), 128B/row; after convert pass: tf32, pair-permuted
#define OFF_AX    0
#define OFF_ARED  65536
#define OFF_B     131072
#define STAGE_B   49152
#define SMEM_BYTES 229376

static __device__ __forceinline__ uint32_t smem_u32(const void* p) {
    uint32_t a;
    asm("{ .reg .u64 t; cvta.to.shared.u64 t, %1; cvt.u32.u64 %0, t; }" : "=r"(a) : "l"(p));
    return a;
}
static __device__ __forceinline__ void cp16(uint32_t dst, const void* src) {
    asm volatile("cp.async.cg.shared.global [%0], [%1], 16;" :: "r"(dst), "l"(src));
}
static __device__ __forceinline__ void cp_commit() {
    asm volatile("cp.async.commit_group;" ::: "memory");
}
static __device__ __forceinline__ void cp_wait1() {
    asm volatile("cp.async.wait_group 1;" ::: "memory");
}
static __device__ __forceinline__ uint32_t f2tf(float f) {
    uint32_t u;
    asm("cvt.rna.tf32.f32 %0, %1;" : "=r"(u) : "f"(f));
    return u;
}
static __device__ __forceinline__ void mma8(float* c, const uint32_t* a,
                                            uint32_t b0, uint32_t b1) {
    asm volatile(
        "mma.sync.aligned.m16n8k8.row.col.f32.tf32.tf32.f32 "
        "{%0,%1,%2,%3}, {%4,%5,%6,%7}, {%8,%9}, {%0,%1,%2,%3};"
        : "+f"(c[0]), "+f"(c[1]), "+f"(c[2]), "+f"(c[3])
        : "r"(a[0]), "r"(a[1]), "r"(a[2]), "r"(a[3]), "r"(b0), "r"(b1));
}
static __device__ __forceinline__ float sigmoidf_(float v) {
    return __fdividef(1.0f, 1.0f + __expf(-v));
}
static __device__ __forceinline__ float tanhf_(float v) {
    return __fdividef(2.0f, 1.0f + __expf(-2.0f * v)) - 1.0f;
}
static __device__ __forceinline__ float lds_f(const char* smem, uint32_t off) {
    return *(const float*)(smem + off);
}

// ---- In-place tf32 convert + (k,k+4) pair-permute of one 48KB B stage ----
// Raw row n (128B): floats k=0..31 of this K-chunk. After pass:
// 8B pair-unit u=kt*4+tq holds (tf32[k=kt*8+tq], tf32[k+4]) at physical unit u^((n&3)<<2).
// Tasks are XOR-orbit pairs of 32B blocks -> thread-local read/write, no hazards.
static __device__ __forceinline__ void convert_B_stage(char* Bst, int tid) {
#pragma unroll
    for (int j = 0; j < 2; ++j) {
        int ti = tid + j * 512;
        if (ti < 768) {
            int n = ti >> 1, p = ti & 1, m = n & 3;
            int b0 = (m <= 1) ? 2 * p : p;
            int b1 = (m == 0) ? (b0 + 1) : (b0 ^ m);
            char* rp = Bst + n * 128;
            float4 x0 = *(float4*)(rp + b0 * 32);
            float4 x1 = *(float4*)(rp + b0 * 32 + 16);
            float4 y0 = *(float4*)(rp + b1 * 32);
            float4 y1 = *(float4*)(rp + b1 * 32 + 16);
            uint4 o0 = make_uint4(f2tf(x0.x), f2tf(x1.x), f2tf(x0.y), f2tf(x1.y));
            uint4 o1 = make_uint4(f2tf(x0.z), f2tf(x1.z), f2tf(x0.w), f2tf(x1.w));
            uint4 q0 = make_uint4(f2tf(y0.x), f2tf(y1.x), f2tf(y0.y), f2tf(y1.y));
            uint4 q1 = make_uint4(f2tf(y0.z), f2tf(y1.z), f2tf(y0.w), f2tf(y1.w));
            *(uint4*)(rp + (b0 ^ m) * 32)      = o0;
            *(uint4*)(rp + (b0 ^ m) * 32 + 16) = o1;
            *(uint4*)(rp + (b1 ^ m) * 32)      = q0;
            *(uint4*)(rp + (b1 ^ m) * 32 + 16) = q1;
        }
    }
}

template <bool CVT>
static __device__ __forceinline__ uint32_t maybe_tf(float v) {
    return CVT ? f2tf(v) : __float_as_uint(v);
}

// One K=32 chunk of MMAs. A: old 16B-swizzled layout. B: pair-permuted tf32.
template <bool CVT>
static __device__ __forceinline__ void chunk_mma(
    const char* As, const char* Bs, float* acc, uint32_t ab0, uint32_t xa,
    uint32_t c3, uint32_t roff, const uint32_t* bko, int tq) {
#pragma unroll
    for (int kt = 0; kt < 4; ++kt) {
        uint32_t kb  = (c3 * 32 + kt * 8 + tq) * 4;
        uint32_t ka  = kb ^ xa;
        uint32_t ka2 = (kb + 16) ^ xa;
        uint32_t afr[2][4];
#pragma unroll
        for (int m = 0; m < 2; ++m) {
            uint32_t ab = ab0 + m * 8192;
            afr[m][0] = maybe_tf<CVT>(lds_f(As, ab + ka));
            afr[m][1] = maybe_tf<CVT>(lds_f(As, ab + 4096 + ka));
            afr[m][2] = maybe_tf<CVT>(lds_f(As, ab + ka2));
            afr[m][3] = maybe_tf<CVT>(lds_f(As, ab + 4096 + ka2));
        }
        const char* Bp = Bs + roff + bko[kt];
#pragma unroll
        for (int nt = 0; nt < 12; ++nt) {
            int C = (nt < 4) ? nt * 1024
                             : (nt < 8) ? 16384 + (nt - 4) * 1024
                                        : 32768 + (nt - 8) * 1024;
            uint2 b = *(const uint2*)(Bp + C);
            mma8(&acc[(0 * 12 + nt) * 4], afr[0], b.x, b.y);
            mma8(&acc[(1 * 12 + nt) * 4], afr[1], b.x, b.y);
        }
    }
}

__global__ void __launch_bounds__(THREADS)
gru_gnn_kernel(const float* __restrict__ x, const float* __restrict__ h,
               const float* __restrict__ w_ih, const float* __restrict__ w_hh,
               const float* __restrict__ b_ih, const float* __restrict__ b_hh,
               const int* __restrict__ src, float* __restrict__ out) {
    extern __shared__ char smem[];
    uint32_t sb = smem_u32(smem);
    const int tid  = threadIdx.x;
    const int wid  = tid >> 5;
    const int lane = tid & 31;
    const int rg   = wid >> 2;     // row group: 32 rows
    const int g    = wid & 3;      // col group: 32 gate cols
    const int tq   = lane & 3;
    const int tg   = lane >> 2;
    const long m0  = (long)blockIdx.x * TM;

    // ---- Issue A tiles (x, red=h[src], 16B-swizzled) + B0 (group0), B1 (group1, linear)
    {
#pragma unroll
        for (int j = 0; j < 8; ++j) {
            int idx = tid + j * THREADS;          // 0..4095
            int r = idx >> 5, u = idx & 31;
            long row = m0 + r;
            if (row >= N_NODES) row = N_NODES - 1;
            uint32_t sw = (uint32_t)(r * 512 + ((u * 16) ^ ((r & 7) * 16)));
            cp16(sb + OFF_AX + sw, x + row * HD + u * 4);
            int srow = __ldg(src + row);
            cp16(sb + OFF_ARED + sw, h + (long)srow * HD + u * 4);
        }
#pragma unroll
        for (int j = 0; j < 6; ++j) {             // B chunk 0: w_ih K[0..32), linear
            int idx = tid + j * THREADS;          // 0..3071 (16B units)
            cp16(sb + OFF_B + idx * 16, w_ih + (idx >> 3) * HD + (idx & 7) * 4);
        }
        cp_commit();
#pragma unroll
        for (int j = 0; j < 6; ++j) {             // B chunk 1: w_ih K[32..64), linear
            int idx = tid + j * THREADS;
            cp16(sb + OFF_B + STAGE_B + idx * 16,
                 w_ih + (idx >> 3) * HD + 32 + (idx & 7) * 4);
        }
        cp_commit();
    }

    float acc[96];   // [m(2)][nt(12)][q(4)]; nt 0-3 = r, 4-7 = z, 8-11 = n
#pragma unroll
    for (int i = 0; i < 96; ++i) acc[i] = 0.0f;

    const int r0 = rg * 32 + tg;
    const uint32_t ab0  = (uint32_t)(r0 * 512);
    const uint32_t xa   = (uint32_t)((r0 & 7) * 16);
    const uint32_t roff = (uint32_t)((g * 32 + tg) * 128);
    uint32_t bko[4];
#pragma unroll
    for (int kt = 0; kt < 4; ++kt)
        bko[kt] = (uint32_t)((((kt * 4 + tq) ^ ((tg & 3) << 2))) * 8);

#pragma unroll 1
    for (int c = 0; c < 8; ++c) {
        cp_wait1();
        __syncthreads();                     // raw stage + (c==0: A) visible

        convert_B_stage(smem + OFF_B + (c & 1) * STAGE_B, tid);
        if (c == 0) {
            // pre-convert A_x to tf32 in place (element-wise, race-free)
            uint4* ax = (uint4*)(smem + OFF_AX);
#pragma unroll
            for (int j = 0; j < 8; ++j) {
                uint4 v = ax[tid + j * 512];
                v.x = f2tf(__uint_as_float(v.x));
                v.y = f2tf(__uint_as_float(v.y));
                v.z = f2tf(__uint_as_float(v.z));
                v.w = f2tf(__uint_as_float(v.w));
                ax[tid + j * 512] = v;
            }
        }
        __syncthreads();                     // converted data visible

        const char* Bs = smem + OFF_B + (c & 1) * STAGE_B;
        if (c < 4)
            chunk_mma<false>(smem + OFF_AX, Bs, acc, ab0, xa, (uint32_t)(c & 3),
                             roff, bko, tq);
        else
            chunk_mma<true>(smem + OFF_ARED, Bs, acc, ab0, xa, (uint32_t)(c & 3),
                            roff, bko, tq);

        __syncthreads();                     // stage (c&1) free to refill
        if (c + 2 < 8) {
            const float* wsrc = ((c + 2) >= 4) ? w_hh : w_ih;
            int k0 = ((c + 2) & 3) * 32;
            uint32_t stb = (uint32_t)(OFF_B + (c & 1) * STAGE_B);
#pragma unroll
            for (int j = 0; j < 6; ++j) {
                int idx = tid + j * THREADS;
                cp16(sb + stb + idx * 16, wsrc + (idx >> 3) * HD + k0 + (idx & 7) * 4);
            }
        }
        cp_commit();

        if (c == 3) {
            // pass 0 done: stash i_n into (dead) A_x region, zero n accumulators
            float* st = (float*)(smem + OFF_AX) + wid * 1024 + lane;
#pragma unroll
            for (int m = 0; m < 2; ++m)
#pragma unroll
                for (int nt = 8; nt < 12; ++nt)
#pragma unroll
                    for (int q = 0; q < 4; ++q) {
                        int e = (m * 4 + (nt - 8)) * 4 + q;
                        st[e * 32] = acc[(m * 12 + nt) * 4 + q];
                        acc[(m * 12 + nt) * 4 + q] = 0.0f;
                    }
        }
    }

    // ---- Epilogue: all gate values for (row, j) are thread-local
    const float* st = (const float*)(smem + OFF_AX) + wid * 1024 + lane;
#pragma unroll
    for (int m = 0; m < 2; ++m) {
#pragma unroll
        for (int nt = 0; nt < 4; ++nt) {
#pragma unroll
            for (int qr = 0; qr < 2; ++qr) {
                int rowl = rg * 32 + m * 16 + tg + qr * 8;
                long grow = m0 + rowl;
                int jb = g * 32 + nt * 8 + tq * 2;
                float2 o;
#pragma unroll
                for (int jq = 0; jq < 2; ++jq) {
                    int q = qr * 2 + jq;
                    int j = jb + jq;
                    float rr = acc[(m * 12 + nt) * 4 + q]
                             + __ldg(b_ih + j) + __ldg(b_hh + j);
                    float zz = acc[(m * 12 + nt + 4) * 4 + q]
                             + __ldg(b_ih + 128 + j) + __ldg(b_hh + 128 + j);
                    float hn = acc[(m * 12 + nt + 8) * 4 + q] + __ldg(b_hh + 256 + j);
                    int e = (m * 4 + nt) * 4 + q;
                    float inq = st[e * 32] + __ldg(b_ih + 256 + j);
                    float rgate = sigmoidf_(rr);
                    float zgate = sigmoidf_(zz);
                    float ngate = tanhf_(inq + rgate * hn);
                    float red = lds_f(smem + OFF_ARED,
                                      (uint32_t)(rowl * 512 + ((j * 4) ^ ((rowl & 7) * 16))));
                    (&o.x)[jq] = (1.0f - zgate) * ngate + zgate * red;
                }
                if (grow < N_NODES)
                    *(float2*)(out + grow * HD + jb) = o;
            }
        }
    }
}

extern "C" void kernel_launch(void* const* d_in, const int* in_sizes, int n_in,
                              void* d_out, int out_size) {
    const float* x    = (const float*)d_in[0];
    const float* h    = (const float*)d_in[1];
    const float* w_ih = (const float*)d_in[2];
    const float* w_hh = (const float*)d_in[3];
    const float* b_ih = (const float*)d_in[4];
    const float* b_hh = (const float*)d_in[5];
    const int*   src  = (const int*)d_in[6];
    // d_in[7] = dst = arange(N): segment_sum collapses to a gather; unused.
    float* out = (float*)d_out;

    cudaFuncSetAttribute(gru_gnn_kernel, cudaFuncAttributeMaxDynamicSharedMemorySize,
                         SMEM_BYTES);
    gru_gnn_kernel<<<NTILES, THREADS, SMEM_BYTES>>>(x, h, w_ih, w_hh, b_ih, b_hh,
                                                    src, out);
}

// round 4
// speedup vs baseline: 1.1021x; 1.1021x over previous
#include <cuda_runtime.h>
#include <cstdint>

#define N_NODES 500000
#define HD      128
#define TM      128
#define THREADS 512
#define NTILES  ((N_NODES + TM - 1) / TM)   // 3907

// -------- SMEM layout (bytes, dynamic) --------
// A_x   [128 rows x 64 pair-units(8B)] tf32 (k,k+4) pairs, XOR-(row&3) swizzle; i_n stash later
// A_red same layout (tf32; also serves epilogue `red`)
// B stages: 2 x 48KB, layout [NT(48)][kt(4)][256B block of [tg(8)][tq(4)] 8B pairs]
#define OFF_AX     0
#define OFF_ARED   65536
#define OFF_B      131072
#define STAGE_B    49152
#define SMEM_BYTES 229376

// Global scratch: pre-converted, pre-permuted tf32 weight pairs.
// [c(8)][NT(48)][kt(4)][tg(8)][tq(4)] -> 49152 x 8B = 384KB (c<4: w_ih, else w_hh)
__device__ uint2 BP_scratch[49152];

static __device__ __forceinline__ uint32_t smem_u32(const void* p) {
    uint32_t a;
    asm("{ .reg .u64 t; cvta.to.shared.u64 t, %1; cvt.u32.u64 %0, t; }" : "=r"(a) : "l"(p));
    return a;
}
static __device__ __forceinline__ void cp16(uint32_t dst, const void* src) {
    asm volatile("cp.async.cg.shared.global [%0], [%1], 16;" :: "r"(dst), "l"(src));
}
static __device__ __forceinline__ void cp_commit() {
    asm volatile("cp.async.commit_group;" ::: "memory");
}
static __device__ __forceinline__ void cp_wait1() {
    asm volatile("cp.async.wait_group 1;" ::: "memory");
}
static __device__ __forceinline__ uint32_t f2tf(float f) {
    uint32_t u;
    asm("cvt.rna.tf32.f32 %0, %1;" : "=r"(u) : "f"(f));
    return u;
}
static __device__ __forceinline__ void mma8(float* c, const uint32_t* a,
                                            uint32_t b0, uint32_t b1) {
    asm volatile(
        "mma.sync.aligned.m16n8k8.row.col.f32.tf32.tf32.f32 "
        "{%0,%1,%2,%3}, {%4,%5,%6,%7}, {%8,%9}, {%0,%1,%2,%3};"
        : "+f"(c[0]), "+f"(c[1]), "+f"(c[2]), "+f"(c[3])
        : "r"(a[0]), "r"(a[1]), "r"(a[2]), "r"(a[3]), "r"(b0), "r"(b1));
}
static __device__ __forceinline__ float sigmoidf_(float v) {
    return __fdividef(1.0f, 1.0f + __expf(-v));
}
static __device__ __forceinline__ float tanhf_(float v) {
    return __fdividef(2.0f, 1.0f + __expf(-2.0f * v)) - 1.0f;
}
static __device__ __forceinline__ float lds_f(const char* smem, uint32_t off) {
    return *(const float*)(smem + off);
}

// ---- Prep: convert weights to tf32 fragment-pair layout in global scratch ----
__global__ void prep_weights(const float* __restrict__ w_ih,
                             const float* __restrict__ w_hh) {
    int p = blockIdx.x * blockDim.x + threadIdx.x;   // 0..49151
    int tq = p & 3;
    int r  = p >> 2;
    int tg = r & 7;  r >>= 3;
    int kt = r & 3;  r >>= 2;
    int nt = r % 48;
    int c  = r / 48;
    const float* W = (c < 4) ? w_ih : w_hh;
    int row = nt * 8 + tg;
    int k   = (c & 3) * 32 + kt * 8 + tq;
    uint2 v;
    v.x = f2tf(W[row * HD + k]);
    v.y = f2tf(W[row * HD + k + 4]);
    BP_scratch[p] = v;
}

__global__ void __launch_bounds__(THREADS)
gru_gnn_kernel(const float* __restrict__ x, const float* __restrict__ h,
               const float* __restrict__ b_ih, const float* __restrict__ b_hh,
               const int* __restrict__ src, float* __restrict__ out) {
    extern __shared__ char smem[];
    uint32_t sb = smem_u32(smem);
    const int tid  = threadIdx.x;
    const int wid  = tid >> 5;
    const int lane = tid & 31;
    const int rg   = wid >> 2;      // row group: 32 rows
    const int g    = wid & 3;       // col group: 32 gate cols
    const int tq   = lane & 3;
    const int tg   = lane >> 2;
    const long m0  = (long)blockIdx.x * TM;
    const char* bp = (const char*)BP_scratch;

    // ---- Preload B stages 0,1 (linear 48KB copies from L2-resident scratch)
#pragma unroll
    for (int j = 0; j < 6; ++j) {
        int idx = tid + j * THREADS;
        cp16(sb + OFF_B + idx * 16, bp + idx * 16);
    }
    cp_commit();
#pragma unroll
    for (int j = 0; j < 6; ++j) {
        int idx = tid + j * THREADS;
        cp16(sb + OFF_B + STAGE_B + idx * 16, bp + STAGE_B + idx * 16);
    }
    cp_commit();

    // ---- A prologue: LDG -> cvt -> (k,k+4) pair pack -> swizzled STS
    {
        int r = tid >> 2, q = tid & 3;              // 4 threads per 128-float row
        long row = m0 + r;
        if (row >= N_NODES) row = N_NODES - 1;
        int srow = __ldg(src + row);
        const float* xr = x + row * HD;
        const float* hr = h + (long)srow * HD;
        uint32_t rbase = (uint32_t)(r * 512);
        uint32_t xr3   = (uint32_t)((r & 3) << 2);
#pragma unroll
        for (int gq = 0; gq < 4; ++gq) {
            int jg = q * 4 + gq;                    // 64B group: floats [8jg..8jg+7]
            uint32_t ub = ((uint32_t)(jg * 4) ^ xr3) * 8;
            float4 lo = *(const float4*)(xr + jg * 8);
            float4 hi = *(const float4*)(xr + jg * 8 + 4);
            *(uint4*)(smem + OFF_AX + rbase + ub) =
                make_uint4(f2tf(lo.x), f2tf(hi.x), f2tf(lo.y), f2tf(hi.y));
            *(uint4*)(smem + OFF_AX + rbase + ub + 16) =
                make_uint4(f2tf(lo.z), f2tf(hi.z), f2tf(lo.w), f2tf(hi.w));
            float4 l2 = *(const float4*)(hr + jg * 8);
            float4 h2 = *(const float4*)(hr + jg * 8 + 4);
            *(uint4*)(smem + OFF_ARED + rbase + ub) =
                make_uint4(f2tf(l2.x), f2tf(h2.x), f2tf(l2.y), f2tf(h2.y));
            *(uint4*)(smem + OFF_ARED + rbase + ub + 16) =
                make_uint4(f2tf(l2.z), f2tf(h2.z), f2tf(l2.w), f2tf(h2.w));
        }
    }

    float acc[96];   // [m(2)][nt(12)][q(4)]; nt 0-3 = r, 4-7 = z, 8-11 = n
#pragma unroll
    for (int i = 0; i < 96; ++i) acc[i] = 0.0f;

    const uint32_t arow0 = (uint32_t)((rg * 32 + tg) * 512);
    const int      t3    = tg & 3;
    const uint32_t kq    = (uint32_t)(tq * 8);
    const uint32_t bgl   = (uint32_t)(g * 4096 + lane * 8);

#pragma unroll 1
    for (int c = 0; c < 8; ++c) {
        cp_wait1();
        __syncthreads();

        const char* As = smem + ((c < 4) ? OFF_AX : OFF_ARED) + (c & 3) * 128;
        const char* Bs = smem + OFF_B + (c & 1) * STAGE_B + bgl;

#pragma unroll
        for (int kt = 0; kt < 4; ++kt) {
            uint32_t ao = (uint32_t)((kt ^ t3) * 32) + kq;
            uint2 a00 = *(const uint2*)(As + arow0 + ao);
            uint2 a01 = *(const uint2*)(As + arow0 + 4096 + ao);
            uint2 a10 = *(const uint2*)(As + arow0 + 8192 + ao);
            uint2 a11 = *(const uint2*)(As + arow0 + 12288 + ao);
            uint32_t af0[4] = {a00.x, a01.x, a00.y, a01.y};
            uint32_t af1[4] = {a10.x, a11.x, a10.y, a11.y};
#pragma unroll
            for (int nt = 0; nt < 12; ++nt) {
                int off = (nt >> 2) * 16384 + (nt & 3) * 1024 + kt * 256;
                uint2 b = *(const uint2*)(Bs + off);
                mma8(&acc[nt * 4],        af0, b.x, b.y);
                mma8(&acc[(12 + nt) * 4], af1, b.x, b.y);
            }
        }

        __syncthreads();                      // stage (c&1) free to refill
        if (c + 2 < 8) {
            uint32_t stb = (uint32_t)(OFF_B + (c & 1) * STAGE_B);
            const char* srcb = bp + (c + 2) * STAGE_B;
#pragma unroll
            for (int j = 0; j < 6; ++j) {
                int idx = tid + j * THREADS;
                cp16(sb + stb + idx * 16, srcb + idx * 16);
            }
        }
        cp_commit();

        if (c == 3) {
            // pass 0 done: stash i_n into (dead) A_x region, zero n accumulators
            float* st = (float*)(smem + OFF_AX) + wid * 1024 + lane;
#pragma unroll
            for (int m = 0; m < 2; ++m)
#pragma unroll
                for (int nt = 8; nt < 12; ++nt)
#pragma unroll
                    for (int q = 0; q < 4; ++q) {
                        int e = (m * 4 + (nt - 8)) * 4 + q;
                        st[e * 32] = acc[(m * 12 + nt) * 4 + q];
                        acc[(m * 12 + nt) * 4 + q] = 0.0f;
                    }
        }
    }

    // ---- Epilogue: all gate values for (row, j) are thread-local
    const float* st = (const float*)(smem + OFF_AX) + wid * 1024 + lane;
#pragma unroll
    for (int m = 0; m < 2; ++m) {
#pragma unroll
        for (int nt = 0; nt < 4; ++nt) {
#pragma unroll
            for (int qr = 0; qr < 2; ++qr) {
                int rowl = rg * 32 + m * 16 + tg + qr * 8;
                long grow = m0 + rowl;
                int jb = g * 32 + nt * 8 + tq * 2;
                float2 o;
#pragma unroll
                for (int jq = 0; jq < 2; ++jq) {
                    int q = qr * 2 + jq;
                    int j = jb + jq;
                    float rr = acc[(m * 12 + nt) * 4 + q]
                             + __ldg(b_ih + j) + __ldg(b_hh + j);
                    float zz = acc[(m * 12 + nt + 4) * 4 + q]
                             + __ldg(b_ih + 128 + j) + __ldg(b_hh + 128 + j);
                    float hn = acc[(m * 12 + nt + 8) * 4 + q] + __ldg(b_hh + 256 + j);
                    int e = (m * 4 + nt) * 4 + q;
                    float inq = st[e * 32] + __ldg(b_ih + 256 + j);
                    float rgate = sigmoidf_(rr);
                    float zgate = sigmoidf_(zz);
                    float ngate = tanhf_(inq + rgate * hn);
                    // red from A_red pair layout (tf32 value)
                    uint32_t u = (uint32_t)(((j >> 3) * 4 + (j & 3)) ^ ((rowl & 3) << 2));
                    uint32_t roff = (uint32_t)(rowl * 512) + u * 8 + ((j & 4) ? 4u : 0u);
                    float red = lds_f(smem + OFF_ARED, roff);
                    (&o.x)[jq] = (1.0f - zgate) * ngate + zgate * red;
                }
                if (grow < N_NODES)
                    *(float2*)(out + grow * HD + jb) = o;
            }
        }
    }
}

extern "C" void kernel_launch(void* const* d_in, const int* in_sizes, int n_in,
                              void* d_out, int out_size) {
    const float* x    = (const float*)d_in[0];
    const float* h    = (const float*)d_in[1];
    const float* w_ih = (const float*)d_in[2];
    const float* w_hh = (const float*)d_in[3];
    const float* b_ih = (const float*)d_in[4];
    const float* b_hh = (const float*)d_in[5];
    const int*   src  = (const int*)d_in[6];
    // d_in[7] = dst = arange(N): segment_sum collapses to a gather; unused.
    float* out = (float*)d_out;

    prep_weights<<<96, 512>>>(w_ih, w_hh);

    cudaFuncSetAttribute(gru_gnn_kernel, cudaFuncAttributeMaxDynamicSharedMemorySize,
                         SMEM_BYTES);
    gru_gnn_kernel<<<NTILES, THREADS, SMEM_BYTES>>>(x, h, b_ih, b_hh, src, out);
}

// round 5
// speedup vs baseline: 1.5548x; 1.4107x over previous
#include <cuda_runtime.h>
#include <cstdint>

#define N_NODES 500000
#define HD      128
#define TM      128
#define THREADS 512
#define NTILES  ((N_NODES + TM - 1) / TM)   // 3907

// -------- SMEM layout (bytes, dynamic) --------
// A_x   [128 rows x 128 f32], 512B/row, xor-16 swizzle (i_n stash after pass 0)
// A_red [128 rows x 128 f32], same swizzle, exact f32 (cvt on the fly for MMA)
// B stages: 2 x 48KB prepacked tf32 pairs: [NT(48)][kt(4)][tg(8)][tq(4)] uint2
#define OFF_AX     0
#define OFF_ARED   65536
#define OFF_B      131072
#define STAGE_B    49152
#define SMEM_BYTES 229376

// Global scratch: pre-converted, pre-permuted tf32 weight pairs.
// [c(8)][NT(48)][kt(4)][tg(8)][tq(4)] -> 49152 x 8B = 384KB (c<4: w_ih, else w_hh)
__device__ uint2 BP_scratch[49152];

static __device__ __forceinline__ uint32_t smem_u32(const void* p) {
    uint32_t a;
    asm("{ .reg .u64 t; cvta.to.shared.u64 t, %1; cvt.u32.u64 %0, t; }" : "=r"(a) : "l"(p));
    return a;
}
static __device__ __forceinline__ void cp16(uint32_t dst, const void* src) {
    asm volatile("cp.async.cg.shared.global [%0], [%1], 16;" :: "r"(dst), "l"(src));
}
static __device__ __forceinline__ void cp_commit() {
    asm volatile("cp.async.commit_group;" ::: "memory");
}
static __device__ __forceinline__ void cp_wait1() {
    asm volatile("cp.async.wait_group 1;" ::: "memory");
}
static __device__ __forceinline__ uint32_t f2tf(float f) {
    uint32_t u;
    asm("cvt.rna.tf32.f32 %0, %1;" : "=r"(u) : "f"(f));
    return u;
}
static __device__ __forceinline__ void mma8(float* c, const uint32_t* a,
                                            uint32_t b0, uint32_t b1) {
    asm volatile(
        "mma.sync.aligned.m16n8k8.row.col.f32.tf32.tf32.f32 "
        "{%0,%1,%2,%3}, {%4,%5,%6,%7}, {%8,%9}, {%0,%1,%2,%3};"
        : "+f"(c[0]), "+f"(c[1]), "+f"(c[2]), "+f"(c[3])
        : "r"(a[0]), "r"(a[1]), "r"(a[2]), "r"(a[3]), "r"(b0), "r"(b1));
}
static __device__ __forceinline__ float sigmoidf_(float v) {
    return __fdividef(1.0f, 1.0f + __expf(-v));
}
static __device__ __forceinline__ float tanhf_(float v) {
    return __fdividef(2.0f, 1.0f + __expf(-2.0f * v)) - 1.0f;
}
static __device__ __forceinline__ float lds_f(const char* smem, uint32_t off) {
    return *(const float*)(smem + off);
}

// ---- Prep: convert weights to tf32 fragment-pair layout in global scratch ----
__global__ void prep_weights(const float* __restrict__ w_ih,
                             const float* __restrict__ w_hh) {
    int p = blockIdx.x * blockDim.x + threadIdx.x;   // 0..49151
    int tq = p & 3;
    int r  = p >> 2;
    int tg = r & 7;  r >>= 3;
    int kt = r & 3;  r >>= 2;
    int nt = r % 48;
    int c  = r / 48;
    const float* W = (c < 4) ? w_ih : w_hh;
    int row = nt * 8 + tg;
    int k   = (c & 3) * 32 + kt * 8 + tq;
    uint2 v;
    v.x = f2tf(W[row * HD + k]);
    v.y = f2tf(W[row * HD + k + 4]);
    BP_scratch[p] = v;
}

__global__ void __launch_bounds__(THREADS)
gru_gnn_kernel(const float* __restrict__ x, const float* __restrict__ h,
               const float* __restrict__ b_ih, const float* __restrict__ b_hh,
               const int* __restrict__ src, float* __restrict__ out) {
    extern __shared__ char smem[];
    uint32_t sb = smem_u32(smem);
    const int tid  = threadIdx.x;
    const int wid  = tid >> 5;
    const int lane = tid & 31;
    const int rg   = wid >> 2;     // row group: 32 rows
    const int g    = wid & 3;      // col group: 32 gate cols
    const int tq   = lane & 3;
    const int tg   = lane >> 2;
    const long m0  = (long)blockIdx.x * TM;
    const char* bp = (const char*)BP_scratch;

    // ---- Group 0: A tiles (x, red=h[src], async, 16B-xor swizzle, f32) + B stage 0
    {
#pragma unroll
        for (int j = 0; j < 8; ++j) {
            int idx = tid + j * THREADS;          // 0..4095
            int r = idx >> 5, u = idx & 31;
            long row = m0 + r;
            if (row >= N_NODES) row = N_NODES - 1;
            uint32_t sw = (uint32_t)(r * 512 + ((u * 16) ^ ((r & 7) * 16)));
            cp16(sb + OFF_AX + sw, x + row * HD + u * 4);
            int srow = __ldg(src + row);
            cp16(sb + OFF_ARED + sw, h + (long)srow * HD + u * 4);
        }
#pragma unroll
        for (int j = 0; j < 6; ++j) {             // B stage 0 <- scratch chunk 0
            int idx = tid + j * THREADS;
            cp16(sb + OFF_B + idx * 16, bp + idx * 16);
        }
        cp_commit();
#pragma unroll
        for (int j = 0; j < 6; ++j) {             // B stage 1 <- scratch chunk 1
            int idx = tid + j * THREADS;
            cp16(sb + OFF_B + STAGE_B + idx * 16, bp + STAGE_B + idx * 16);
        }
        cp_commit();
    }

    float acc[96];   // [m(2)][nt(12)][q(4)]; nt 0-3 = r, 4-7 = z, 8-11 = n
#pragma unroll
    for (int i = 0; i < 96; ++i) acc[i] = 0.0f;

    const int r0 = rg * 32 + tg;
    const uint32_t ab0 = (uint32_t)(r0 * 512);
    const uint32_t xa  = (uint32_t)((r0 & 7) * 16);
    const uint32_t bgl = (uint32_t)(g * 4096 + lane * 8);

#pragma unroll 1
    for (int c = 0; c < 8; ++c) {
        cp_wait1();
        __syncthreads();

        const char* As = smem + ((c < 4) ? OFF_AX : OFF_ARED);
        const char* Bs = smem + OFF_B + (c & 1) * STAGE_B + bgl;

#pragma unroll
        for (int kt = 0; kt < 4; ++kt) {
            uint32_t kb  = (uint32_t)(((c & 3) * 32 + kt * 8 + tq) * 4);
            uint32_t ka  = kb ^ xa;
            uint32_t ka2 = (kb + 16) ^ xa;
            uint32_t afr[2][4];
#pragma unroll
            for (int m = 0; m < 2; ++m) {
                uint32_t ab = ab0 + (uint32_t)(m * 8192);
                afr[m][0] = f2tf(lds_f(As, ab + ka));
                afr[m][1] = f2tf(lds_f(As, ab + 4096 + ka));
                afr[m][2] = f2tf(lds_f(As, ab + ka2));
                afr[m][3] = f2tf(lds_f(As, ab + 4096 + ka2));
            }
#pragma unroll
            for (int nt = 0; nt < 12; ++nt) {
                int off = (nt >> 2) * 16384 + (nt & 3) * 1024 + kt * 256;
                uint2 b = *(const uint2*)(Bs + off);
                mma8(&acc[(0 * 12 + nt) * 4], afr[0], b.x, b.y);
                mma8(&acc[(1 * 12 + nt) * 4], afr[1], b.x, b.y);
            }
        }

        __syncthreads();                      // stage (c&1) free to refill
        if (c + 2 < 8) {
            uint32_t stb = (uint32_t)(OFF_B + (c & 1) * STAGE_B);
            const char* srcb = bp + (c + 2) * STAGE_B;
#pragma unroll
            for (int j = 0; j < 6; ++j) {
                int idx = tid + j * THREADS;
                cp16(sb + stb + idx * 16, srcb + idx * 16);
            }
        }
        cp_commit();

        if (c == 3) {
            // pass 0 done: stash i_n into (dead) A_x region, zero n accumulators
            float* st = (float*)(smem + OFF_AX) + wid * 1024 + lane;
#pragma unroll
            for (int m = 0; m < 2; ++m)
#pragma unroll
                for (int nt = 8; nt < 12; ++nt)
#pragma unroll
                    for (int q = 0; q < 4; ++q) {
                        int e = (m * 4 + (nt - 8)) * 4 + q;
                        st[e * 32] = acc[(m * 12 + nt) * 4 + q];
                        acc[(m * 12 + nt) * 4 + q] = 0.0f;
                    }
        }
    }

    // ---- Epilogue: all gate values for (row, j) are thread-local
    const float* st = (const float*)(smem + OFF_AX) + wid * 1024 + lane;
#pragma unroll
    for (int m = 0; m < 2; ++m) {
#pragma unroll
        for (int nt = 0; nt < 4; ++nt) {
#pragma unroll
            for (int qr = 0; qr < 2; ++qr) {
                int rowl = rg * 32 + m * 16 + tg + qr * 8;
                long grow = m0 + rowl;
                int jb = g * 32 + nt * 8 + tq * 2;
                float2 o;
#pragma unroll
                for (int jq = 0; jq < 2; ++jq) {
                    int q = qr * 2 + jq;
                    int j = jb + jq;
                    float rr = acc[(m * 12 + nt) * 4 + q]
                             + __ldg(b_ih + j) + __ldg(b_hh + j);
                    float zz = acc[(m * 12 + nt + 4) * 4 + q]
                             + __ldg(b_ih + 128 + j) + __ldg(b_hh + 128 + j);
                    float hn = acc[(m * 12 + nt + 8) * 4 + q] + __ldg(b_hh + 256 + j);
                    int e = (m * 4 + nt) * 4 + q;
                    float inq = st[e * 32] + __ldg(b_ih + 256 + j);
                    float rgate = sigmoidf_(rr);
                    float zgate = sigmoidf_(zz);
                    float ngate = tanhf_(inq + rgate * hn);
                    float red = lds_f(smem + OFF_ARED,
                                      (uint32_t)(rowl * 512 + ((j * 4) ^ ((rowl & 7) * 16))));
                    (&o.x)[jq] = (1.0f - zgate) * ngate + zgate * red;
                }
                if (grow < N_NODES)
                    *(float2*)(out + grow * HD + jb) = o;
            }
        }
    }
}

extern "C" void kernel_launch(void* const* d_in, const int* in_sizes, int n_in,
                              void* d_out, int out_size) {
    const float* x    = (const float*)d_in[0];
    const float* h    = (const float*)d_in[1];
    const float* w_ih = (const float*)d_in[2];
    const float* w_hh = (const float*)d_in[3];
    const float* b_ih = (const float*)d_in[4];
    const float* b_hh = (const float*)d_in[5];
    const int*   src  = (const int*)d_in[6];
    // d_in[7] = dst = arange(N): segment_sum collapses to a gather; unused.
    float* out = (float*)d_out;

    prep_weights<<<96, 512>>>(w_ih, w_hh);

    cudaFuncSetAttribute(gru_gnn_kernel, cudaFuncAttributeMaxDynamicSharedMemorySize,
                         SMEM_BYTES);
    gru_gnn_kernel<<<NTILES, THREADS, SMEM_BYTES>>>(x, h, b_ih, b_hh, src, out);
}